// round 17
// baseline (speedup 1.0000x reference)
#include <cuda_runtime.h>
#include <cuda_fp16.h>
#include <cstdint>

#define N_NODES 50000
#define N_EDGES 600000
#define D_IN    128
#define D_HID   1024
#define D_OUT   128

// ---------------------------------------------------------------------------
// Device-global scratch. ONLY referenced from device code (host-shadow bug).
// ---------------------------------------------------------------------------
__device__ float  g_h[(size_t)N_NODES * D_IN];
__device__ __half g_feat_h[(size_t)N_NODES * D_IN];  // fp16 copy of feat
__device__ __half g_w1t[(size_t)D_HID * D_IN];       // W1^T [1024][128] fp16
__device__ __half g_w2t[(size_t)D_OUT * D_HID];      // W2^T [128][1024] fp16

// ---------------------------------------------------------------------------
// Helpers. Convention: generic pointers (smem + off) for C++ ld/st;
// shared-space 32-bit addresses (sb + off) ONLY for ldmatrix/cp.async.
// ---------------------------------------------------------------------------
__device__ __forceinline__ uint32_t smem_u32(const void* p) {
    uint32_t a;
    asm("{ .reg .u64 t; cvta.to.shared.u64 t, %1; cvt.u32.u64 %0, t; }" : "=r"(a) : "l"(p));
    return a;
}
#define SW128(x) ((x) ^ (((x) >> 3) & 0x70))

// 128-row x 128-k fp16 tile: two 16KB sub-tiles (k-bytes [0,128),[128,256)), SW128.
__device__ __forceinline__ uint32_t toff(int row, int kbyte) {
    uint32_t w = (uint32_t)(row * 128 + (kbyte & 127));
    return (uint32_t)((kbyte >> 7) * 16384) + SW128(w);
}

__device__ __forceinline__ void ldsm_x4(uint32_t (&r)[4], uint32_t addr) {
    asm volatile("ldmatrix.sync.aligned.m8n8.x4.shared.b16 {%0,%1,%2,%3}, [%4];"
                 : "=r"(r[0]), "=r"(r[1]), "=r"(r[2]), "=r"(r[3]) : "r"(addr));
}
__device__ __forceinline__ void mma_f16(float (&d)[4], const uint32_t (&a)[4],
                                        uint32_t b0, uint32_t b1) {
    asm volatile(
        "mma.sync.aligned.m16n8k16.row.col.f32.f16.f16.f32 "
        "{%0,%1,%2,%3}, {%4,%5,%6,%7}, {%8,%9}, {%0,%1,%2,%3};"
        : "+f"(d[0]), "+f"(d[1]), "+f"(d[2]), "+f"(d[3])
        : "r"(a[0]), "r"(a[1]), "r"(a[2]), "r"(a[3]), "r"(b0), "r"(b1));
}
__device__ __forceinline__ uint32_t pack_h2(float x0, float x1) {
    __half2 p = __floats2half2_rn(x0, x1);
    return *reinterpret_cast<uint32_t*>(&p);
}
__device__ __forceinline__ void cp16(uint32_t dst, const void* src) {
    asm volatile("cp.async.cg.shared.global [%0], [%1], 16;" :: "r"(dst), "l"(src));
}
#define BAR_SYNC(id, cnt)   asm volatile("bar.sync %0, %1;"   :: "r"(id), "r"(cnt) : "memory")
#define BAR_ARRIVE(id, cnt) asm volatile("bar.arrive %0, %1;" :: "r"(id), "r"(cnt) : "memory")
// Barrier ids: 1,2 = FULL(slot0,1); 3,4 = EMPTY(slot0,1); 5 = prod-internal; 6 = cons-internal

// ---------------------------------------------------------------------------
// Phase 1: fused prelude — zero g_h + weights->fp16 + feat->fp16.  (R16, proven)
// ---------------------------------------------------------------------------
__global__ void prelude_kernel(const float* __restrict__ W1, const float* __restrict__ W2,
                               const float* __restrict__ feat) {
    int b = blockIdx.x;
    if (b < 6250) {
        int i = b * 256 + threadIdx.x;
        if (i < N_NODES * D_IN / 4)
            reinterpret_cast<float4*>(g_h)[i] = make_float4(0.f, 0.f, 0.f, 0.f);
    } else if (b < 6762) {
        int i = (b - 6250) * 256 + threadIdx.x;      // over W1 [128][1024]
        int k = i >> 10, n = i & 1023;
        g_w1t[(size_t)n * D_IN + k] = __float2half(W1[i]);
    } else if (b < 7274) {
        int i = (b - 6762) * 256 + threadIdx.x;      // over W2 [1024][128]
        int k = i >> 7, n = i & 127;
        g_w2t[(size_t)n * D_HID + k] = __float2half(W2[i]);
    } else {
        int i = (b - 7274) * 256 + threadIdx.x;      // 8 floats per thread
        const float4* fp = reinterpret_cast<const float4*>(feat) + (size_t)i * 2;
        float4 f0 = fp[0], f1 = fp[1];
        uint4 v;
        v.x = pack_h2(f0.x, f0.y); v.y = pack_h2(f0.z, f0.w);
        v.z = pack_h2(f1.x, f1.y); v.w = pack_h2(f1.z, f1.w);
        reinterpret_cast<uint4*>(g_feat_h)[i] = v;
    }
}

// ---------------------------------------------------------------------------
// Phase 2: scatter (R16, proven). fp16 feat reads, fp32 float4 atomics.
// ---------------------------------------------------------------------------
__global__ void scatter_kernel(const float* __restrict__ edge_feat,
                               const int*   __restrict__ src,
                               const int*   __restrict__ dst) {
    int warp = (blockIdx.x * blockDim.x + threadIdx.x) >> 5;
    int lane = threadIdx.x & 31;
    if (warp >= N_EDGES) return;
    int s = src[warp], d = dst[warp];
    uint2 fh = reinterpret_cast<const uint2*>(g_feat_h + (size_t)s * D_IN)[lane];
    float4 b = reinterpret_cast<const float4*>(edge_feat + (size_t)warp * D_IN)[lane];
    __half2 h01 = *reinterpret_cast<__half2*>(&fh.x);
    __half2 h23 = *reinterpret_cast<__half2*>(&fh.y);
    float2 f01 = __half22float2(h01);
    float2 f23 = __half22float2(h23);
    float4 m = make_float4(f01.x + b.x, f01.y + b.y, f23.x + b.z, f23.y + b.w);
    atomicAdd(reinterpret_cast<float4*>(g_h + (size_t)d * D_IN + lane * 4), m);
}

// ---------------------------------------------------------------------------
// Phase 3: warp-specialized fused MLP.
// Warps 0-7 (producers): stage1 A@W1c -> bias/relu -> H ping-pong.
// Warps 8-15 (consumers): stage2 oacc += H@W2c; epilogue.
// Both groups: 4(M)x2(N) warp grid, 32x64 tiles (R15-proven mappings).
// Smem: A 32K + H 2x32K + W1 ring 2x32K + W2 ring 2x32K = 224KB.
// ---------------------------------------------------------------------------
#define OFF_A   0
#define OFF_H   32768         // slots at 32768, 65536
#define OFF_W1  98304         // slots at 98304, 131072
#define OFF_W2  163840        // slots at 163840, 196608

__device__ __forceinline__ void load_w1(char* smem, int c, int ptid) {
    const uint32_t base = smem_u32(smem) + OFF_W1 + (c & 1) * 32768;
#pragma unroll
    for (int i = ptid; i < 128 * 16; i += 256) {
        int row = i >> 4, ch = i & 15;
        size_t g = (size_t)(c * 128 + row) * D_IN + ch * 8;
        cp16(base + toff(row, ch * 16), g_w1t + g);
    }
    asm volatile("cp.async.commit_group;" ::: "memory");
}
__device__ __forceinline__ void load_w2(char* smem, int c, int ptid) {
    const uint32_t base = smem_u32(smem) + OFF_W2 + (c & 1) * 32768;
#pragma unroll
    for (int i = ptid; i < 128 * 16; i += 256) {
        int row = i >> 4, ch = i & 15;
        size_t g = (size_t)row * D_HID + c * 128 + ch * 8;
        cp16(base + toff(row, ch * 16), g_w2t + g);
    }
    asm volatile("cp.async.commit_group;" ::: "memory");
}

__global__ __launch_bounds__(512, 1)
void fused_mlp_kernel(const float* __restrict__ b1, const float* __restrict__ b2,
                      float* __restrict__ out) {
    extern __shared__ char smem[];
    const uint32_t sb = smem_u32(smem);
    const int tid = threadIdx.x;
    const int lane = tid & 31;
    const int wid  = tid >> 5;                  // 0..15
    const bool is_prod = (wid < 8);
    const int ptid = tid & 255;                 // 0..255 within group
    const int lwid = wid & 7;
    const int wm = lwid >> 1, wn = lwid & 1;    // 4(M) x 2(N), 32x64 tiles
    const int row0 = blockIdx.x * 128;

    // prologue: each group prefetches its first weight tile
    if (is_prod) load_w1(smem, 0, ptid);
    else         load_w2(smem, 0, ptid);

    // ---- load A = h rows, fp32 -> fp16 (all 512 threads) ----
    for (int c = tid; c < 128 * 16; c += 512) {
        int row = c >> 4, ch = c & 15;
        float4 f0 = make_float4(0.f, 0.f, 0.f, 0.f), f1 = f0;
        if (row0 + row < N_NODES) {
            const float* gp = g_h + (size_t)(row0 + row) * D_IN + ch * 8;
            f0 = *reinterpret_cast<const float4*>(gp);
            f1 = *reinterpret_cast<const float4*>(gp + 4);
        }
        uint4 v;
        v.x = pack_h2(f0.x, f0.y); v.y = pack_h2(f0.z, f0.w);
        v.z = pack_h2(f1.x, f1.y); v.w = pack_h2(f1.z, f1.w);
        *reinterpret_cast<uint4*>(smem + OFF_A + toff(row, ch * 16)) = v;
    }
    __syncthreads();

    if (is_prod) {
        // ================= producers: stage 1 =================
        for (int c = 0; c < 8; c++) {
            const int slot = c & 1;
            BAR_SYNC(5, 256);                       // all producers done reading W1(c-1)
            if (c + 1 < 8) {
                load_w1(smem, c + 1, ptid);
                asm volatile("cp.async.wait_group 1;" ::: "memory");
            } else {
                asm volatile("cp.async.wait_group 0;" ::: "memory");
            }
            const uint32_t wb = sb + OFF_W1 + slot * 32768;

            float hacc[2][8][4];
#pragma unroll
            for (int i = 0; i < 2; i++)
#pragma unroll
                for (int j = 0; j < 8; j++)
#pragma unroll
                    for (int q = 0; q < 4; q++) hacc[i][j][q] = 0.f;

#pragma unroll
            for (int ks = 0; ks < 8; ks++) {
                const int kb = ks * 32;
                uint32_t a[2][4];
#pragma unroll
                for (int mt = 0; mt < 2; mt++) {
                    int arow = wm * 32 + mt * 16 + (lane & 15);
                    ldsm_x4(a[mt], sb + OFF_A + toff(arow, kb + (lane >> 4) * 16));
                }
#pragma unroll
                for (int pn = 0; pn < 4; pn++) {
                    int brow = wn * 64 + pn * 16 + (lane >> 4) * 8 + (lane & 7);
                    uint32_t bh[4];
                    ldsm_x4(bh, wb + toff(brow, kb + ((lane >> 3) & 1) * 16));
#pragma unroll
                    for (int mt = 0; mt < 2; mt++) {
                        mma_f16(hacc[mt][2 * pn],     a[mt], bh[0], bh[1]);
                        mma_f16(hacc[mt][2 * pn + 1], a[mt], bh[2], bh[3]);
                    }
                }
            }

            BAR_SYNC(3 + slot, 512);                // EMPTY[slot]: consumers done with it
            // bias + relu -> H[slot] (fp16), generic pointers
            char* hdst = smem + OFF_H + slot * 32768;
#pragma unroll
            for (int mt = 0; mt < 2; mt++) {
                int r = wm * 32 + mt * 16 + (lane >> 2);
#pragma unroll
                for (int nt = 0; nt < 8; nt++) {
                    int cl = wn * 64 + nt * 8 + (lane & 3) * 2;
                    float bv0 = __ldg(b1 + c * 128 + cl);
                    float bv1 = __ldg(b1 + c * 128 + cl + 1);
                    float x0 = fmaxf(hacc[mt][nt][0] + bv0, 0.f);
                    float x1 = fmaxf(hacc[mt][nt][1] + bv1, 0.f);
                    float x2 = fmaxf(hacc[mt][nt][2] + bv0, 0.f);
                    float x3 = fmaxf(hacc[mt][nt][3] + bv1, 0.f);
                    *reinterpret_cast<uint32_t*>(hdst + toff(r,     cl * 2)) = pack_h2(x0, x1);
                    *reinterpret_cast<uint32_t*>(hdst + toff(r + 8, cl * 2)) = pack_h2(x2, x3);
                }
            }
            asm volatile("membar.cta;" ::: "memory");   // H stores visible before arrive
            BAR_ARRIVE(1 + slot, 512);              // FULL[slot]
        }
    } else {
        // ================= consumers: stage 2 + epilogue =================
        BAR_ARRIVE(3, 512);                         // prime EMPTY0
        BAR_ARRIVE(4, 512);                         // prime EMPTY1

        float oacc[2][8][4];
#pragma unroll
        for (int i = 0; i < 2; i++)
#pragma unroll
            for (int j = 0; j < 8; j++)
#pragma unroll
                for (int q = 0; q < 4; q++) oacc[i][j][q] = 0.f;

        for (int c = 0; c < 8; c++) {
            const int slot = c & 1;
            BAR_SYNC(6, 256);                       // all consumers done reading W2(c-1)
            if (c + 1 < 8) {
                load_w2(smem, c + 1, ptid);
                asm volatile("cp.async.wait_group 1;" ::: "memory");
            } else {
                asm volatile("cp.async.wait_group 0;" ::: "memory");
            }
            BAR_SYNC(1 + slot, 512);                // FULL[slot]: H ready
            const uint32_t wb = sb + OFF_W2 + slot * 32768;
            const uint32_t hb = sb + OFF_H + slot * 32768;

#pragma unroll
            for (int ks = 0; ks < 8; ks++) {
                const int kb = ks * 32;
                uint32_t a[2][4];
#pragma unroll
                for (int mt = 0; mt < 2; mt++) {
                    int arow = wm * 32 + mt * 16 + (lane & 15);
                    ldsm_x4(a[mt], hb + toff(arow, kb + (lane >> 4) * 16));
                }
#pragma unroll
                for (int pn = 0; pn < 4; pn++) {
                    int brow = wn * 64 + pn * 16 + (lane >> 4) * 8 + (lane & 7);
                    uint32_t bh[4];
                    ldsm_x4(bh, wb + toff(brow, kb + ((lane >> 3) & 1) * 16));
#pragma unroll
                    for (int mt = 0; mt < 2; mt++) {
                        mma_f16(oacc[mt][2 * pn],     a[mt], bh[0], bh[1]);
                        mma_f16(oacc[mt][2 * pn + 1], a[mt], bh[2], bh[3]);
                    }
                }
            }
            BAR_ARRIVE(3 + slot, 512);              // EMPTY[slot]
        }

        // ---- epilogue: out = oacc + b2 (R15-proven mapping) ----
#pragma unroll
        for (int mt = 0; mt < 2; mt++) {
            int r = row0 + wm * 32 + mt * 16 + (lane >> 2);
#pragma unroll
            for (int nt = 0; nt < 8; nt++) {
                int col = wn * 64 + nt * 8 + (lane & 3) * 2;
                float bv0 = __ldg(b2 + col), bv1 = __ldg(b2 + col + 1);
                if (r < N_NODES)
                    *reinterpret_cast<float2*>(out + (size_t)r * D_OUT + col) =
                        make_float2(oacc[mt][nt][0] + bv0, oacc[mt][nt][1] + bv1);
                if (r + 8 < N_NODES)
                    *reinterpret_cast<float2*>(out + (size_t)(r + 8) * D_OUT + col) =
                        make_float2(oacc[mt][nt][2] + bv0, oacc[mt][nt][3] + bv1);
            }
        }
    }
}

// ---------------------------------------------------------------------------
// Launch: prelude(0), scatter(1), fusedMLP(2)
// ---------------------------------------------------------------------------
extern "C" void kernel_launch(void* const* d_in, const int* in_sizes, int n_in,
                              void* d_out, int out_size) {
    const float* feat = nullptr; const float* edge_feat = nullptr;
    const int*   src  = nullptr; const int*   dst = nullptr;
    const float* W1   = nullptr; const float* b1  = nullptr;
    const float* W2   = nullptr; const float* b2  = nullptr;

    for (int i = 0; i < n_in; i++) {
        long long sz = in_sizes[i];
        if      (sz == (long long)N_NODES * D_IN)  feat = (const float*)d_in[i];
        else if (sz == (long long)N_EDGES * D_IN)  edge_feat = (const float*)d_in[i];
        else if (sz == (long long)N_EDGES) { if (!src) src = (const int*)d_in[i]; else dst = (const int*)d_in[i]; }
        else if (sz == (long long)D_IN * D_HID) { if (!W1) W1 = (const float*)d_in[i]; else W2 = (const float*)d_in[i]; }
        else if (sz == (long long)D_HID)           b1 = (const float*)d_in[i];
        else if (sz == (long long)D_OUT)           b2 = (const float*)d_in[i];
    }
    float* out = (float*)d_out;

    constexpr int SMEM = 229376;   // 224KB
    cudaFuncSetAttribute(fused_mlp_kernel, cudaFuncAttributeMaxDynamicSharedMemorySize, SMEM);

    prelude_kernel<<<10399, 256>>>(W1, W2, feat);
    { int blocks = (N_EDGES + 7) / 8; scatter_kernel<<<blocks, 256>>>(edge_feat, src, dst); }
    {
        dim3 grid((N_NODES + 127) / 128);
        fused_mlp_kernel<<<grid, 512, SMEM>>>(b1, b2, out);
    }
}